// round 7
// baseline (speedup 1.0000x reference)
#include <cuda_runtime.h>
#include <cuda_bf16.h>
#include <cstdint>

// ============================================================================
// hashedLayer on GB300 (sm_103a SASS, PTX target compute_103 => NO tcgen05).
// out[b,i] = sum_j a_ext[b,j] * W[hash_idx[i,j]]
//          = a[B,128] @ Wmat[128,128]^T + bias[i],  bias[i]=W[hash_idx[i,128]]
// Legacy tensor path: mma.sync.m16n8k16 bf16, split-bf16 3 products
// (AH*WH + AL*WH + AH*WL), fp32 register accumulators.
// Persistent CTAs, cp.async staging of next A tile overlapped with compute.
// ============================================================================

#define FAN 128
#define BM 128
#define NTILES 2048          // 262144 / 128
#define GRID 152
#define SW128(o) ((o) ^ (((o) >> 3) & 0x70))

// SMEM layout
#define OFF_BIAS  0          // 512 B
#define OFF_WH    1024       // 32 KB bf16 [128n x 128k] swizzled
#define OFF_WL    (OFF_WH + 32768)
#define OFF_AH    (OFF_WL + 32768)
#define OFF_AL    (OFF_AH + 32768)
#define OFF_STAGE (OFF_AL + 32768)   // 64 KB fp32 staging (linear)
#define SMEM_BYTES (OFF_STAGE + 65536)   // 197632 < 227KB

// Tile byte offset: two 16KB blocks (k<64 / k>=64); within block
// off = row*128 + (k%64)*2, xor-swizzled for conflict-free ldmatrix.
static __device__ __host__ __forceinline__ uint32_t toff(int row, int k) {
    uint32_t off = (uint32_t)row * 128u + ((uint32_t)(k & 63) << 1);
    return (((uint32_t)k >> 6) << 14) + (uint32_t)SW128(off);
}

// W scratch (pre-swizzled, ready for straight copy into SMEM)
__device__ __align__(16) __nv_bfloat16 g_wh[FAN * FAN];
__device__ __align__(16) __nv_bfloat16 g_wl[FAN * FAN];
__device__ float g_bias[FAN];

static __device__ __forceinline__ uint32_t smem_u32(const void* p) {
    uint32_t a;
    asm("{ .reg .u64 t; cvta.to.shared.u64 t, %1; cvt.u32.u64 %0, t; }"
        : "=r"(a) : "l"(p));
    return a;
}

#define LDSM4(r, addr) \
    asm volatile("ldmatrix.sync.aligned.m8n8.x4.shared.b16 {%0,%1,%2,%3}, [%4];" \
        : "=r"((r)[0]), "=r"((r)[1]), "=r"((r)[2]), "=r"((r)[3]) : "r"(addr))

#define MMA16816(d, a, b0, b1) \
    asm volatile("mma.sync.aligned.m16n8k16.row.col.f32.bf16.bf16.f32 " \
        "{%0,%1,%2,%3}, {%4,%5,%6,%7}, {%8,%9}, {%0,%1,%2,%3};" \
        : "+f"((d)[0]), "+f"((d)[1]), "+f"((d)[2]), "+f"((d)[3]) \
        : "r"((a)[0]), "r"((a)[1]), "r"((a)[2]), "r"((a)[3]), "r"(b0), "r"(b1))

#define CP_ASYNC16(dst, src) \
    asm volatile("cp.async.cg.shared.global [%0], [%1], 16;" \
        :: "r"(dst), "l"(src))
#define CP_COMMIT() asm volatile("cp.async.commit_group;" ::: "memory")
#define CP_WAIT0()  asm volatile("cp.async.wait_group 0;" ::: "memory")

// ---------------------------------------------------------------------------
// Kernel 1: gather Wmat = W[hash_idx], split to bf16 hi/lo, pre-swizzled; bias
// hash_idx may be int32 or int64 (JAX x64 ambiguity) — detect at runtime.
// ---------------------------------------------------------------------------
__global__ void __launch_bounds__(256) prep_kernel(
    const float* __restrict__ W, const void* __restrict__ hidx_raw)
{
    __shared__ int s_is64;
    if (threadIdx.x == 0) {
        // int64 values < 4096 -> odd int32 words all zero. P(false-pos) ~ 4096^-16
        const int* p32 = (const int*)hidx_raw;
        int any = 0;
#pragma unroll
        for (int k = 0; k < 16; ++k) any |= p32[2 * k + 1];
        s_is64 = (any == 0) ? 1 : 0;
    }
    __syncthreads();
    const int is64 = s_is64;
    const int* h32 = (const int*)hidx_raw;
    const long long* h64 = (const long long*)hidx_raw;

    int t = blockIdx.x * blockDim.x + threadIdx.x;
    if (t < FAN * FAN) {
        int i = t >> 7;              // output feature n
        int j = t & 127;             // reduction k
        size_t pos = (size_t)i * 129 + j;
        long long idx = is64 ? h64[pos] : (long long)h32[pos];
        float w = W[idx];
        __nv_bfloat16 hi = __float2bfloat16(w);
        float res = w - __bfloat162float(hi);
        uint32_t o = toff(i, j);
        g_wh[o >> 1] = hi;
        g_wl[o >> 1] = __float2bfloat16(res);
    }
    if (t < FAN) {
        size_t pos = (size_t)t * 129 + 128;
        long long idx = is64 ? h64[pos] : (long long)h32[pos];
        g_bias[t] = W[idx];
    }
}

// ---------------------------------------------------------------------------
// Kernel 2: persistent GEMM. Warp layout: 8 warps = 4(m) x 2(n), warp tile
// 32m x 64n. Per k-step: ldmatrix WH(4x4), AH(2x4), AL(2x4) -> 32 mma;
// then WL(4x4) -> 16 mma. cp.async stages next tile during compute.
// ---------------------------------------------------------------------------
__global__ void __launch_bounds__(256, 1)
hashed_gemm_kernel(const float* __restrict__ a, float* __restrict__ out)
{
    extern __shared__ char smem[];
    const uint32_t sbase = smem_u32(smem);
    const int tid = threadIdx.x;
    const int wid = tid >> 5;
    const int lane = tid & 31;

    // ---- load W tiles (already swizzled) + bias into SMEM ----
    {
        const uint4* sh = (const uint4*)g_wh;
        const uint4* sl = (const uint4*)g_wl;
        uint4* dh = (uint4*)(smem + OFF_WH);
        uint4* dl = (uint4*)(smem + OFF_WL);
#pragma unroll
        for (int it = 0; it < 8; ++it) {
            dh[tid + it * 256] = sh[tid + it * 256];
            dl[tid + it * 256] = sl[tid + it * 256];
        }
        if (tid < FAN) ((float*)(smem + OFF_BIAS))[tid] = g_bias[tid];
    }

    // ---- per-lane ldmatrix address components ----
    const int g = lane >> 3, lr = lane & 7;
    const int wm = wid & 3;          // m block: rows wm*32
    const int wn = wid >> 2;         // n block: cols wn*64
    uint32_t rpA[2], axA[2], rpB[4], axB[4];
    const uint32_t kaddA = (uint32_t)((g >> 1) & 1) << 4;   // A: k+8 half
    const uint32_t kaddB = (uint32_t)(g & 1) << 4;          // B: k+8 half
#pragma unroll
    for (int s = 0; s < 2; ++s) {
        int row = wm * 32 + s * 16 + ((g & 1) << 3) + lr;   // A rows
        rpA[s] = (uint32_t)row << 7;
        axA[s] = (uint32_t)(row & 7) << 4;
    }
#pragma unroll
    for (int q = 0; q < 4; ++q) {
        int row = wn * 64 + q * 16 + (((g >> 1) & 1) << 3) + lr;  // B: n rows
        rpB[q] = (uint32_t)row << 7;
        axB[q] = (uint32_t)(row & 7) << 4;
    }
    const uint32_t sWH = sbase + OFF_WH, sWL = sbase + OFF_WL;
    const uint32_t sAH = sbase + OFF_AH, sAL = sbase + OFF_AL;

    // ---- preload per-thread bias pairs into registers (tile-invariant) ----
    __syncthreads();   // bias + W SMEM visible
    float bx[8], by[8];
    {
        const int tr = lane & 3;
        const float* bias_s = (const float*)(smem + OFF_BIAS);
#pragma unroll
        for (int nf = 0; nf < 8; ++nf) {
            int n0 = wn * 64 + nf * 8 + tr * 2;
            bx[nf] = bias_s[n0];
            by[nf] = bias_s[n0 + 1];
        }
    }

    // ---- prologue: stage first tile ----
    {
        int t0 = blockIdx.x;
        if (t0 < NTILES) {
            const char* src = (const char*)(a + (size_t)t0 * BM * FAN);
            uint32_t dst = sbase + OFF_STAGE;
#pragma unroll
            for (int it = 0; it < 16; ++it) {
                uint32_t off = (uint32_t)tid * 16u + (uint32_t)it * 4096u;
                CP_ASYNC16(dst + off, src + off);
            }
        }
        CP_COMMIT();
    }

    for (int t = blockIdx.x; t < NTILES; t += GRID) {
        CP_WAIT0();
        __syncthreads();    // stage(t) complete across all threads

        // ---- convert stage (fp32) -> AH/AL (bf16 hi/lo, swizzled) ----
        {
            const float4* st4 = (const float4*)(smem + OFF_STAGE);
#pragma unroll
            for (int it = 0; it < 16; ++it) {
                int idx = tid + it * 256;        // float4 index 0..4095
                float4 v = st4[idx];
                int row = idx >> 5;
                int k = (idx & 31) << 2;
                __nv_bfloat162 h01 = __floats2bfloat162_rn(v.x, v.y);
                __nv_bfloat162 h23 = __floats2bfloat162_rn(v.z, v.w);
                float lx = v.x - __low2float(h01);
                float ly = v.y - __high2float(h01);
                float lz = v.z - __low2float(h23);
                float lw = v.w - __high2float(h23);
                __nv_bfloat162 l01 = __floats2bfloat162_rn(lx, ly);
                __nv_bfloat162 l23 = __floats2bfloat162_rn(lz, lw);
                uint32_t o = toff(row, k);
                uint2 hp, lp;
                hp.x = *(uint32_t*)&h01; hp.y = *(uint32_t*)&h23;
                lp.x = *(uint32_t*)&l01; lp.y = *(uint32_t*)&l23;
                *(uint2*)(smem + OFF_AH + o) = hp;
                *(uint2*)(smem + OFF_AL + o) = lp;
            }
        }
        __syncthreads();    // STS visible before ldmatrix; stage reads done

        // ---- kick off cp.async for next tile (overlaps compute) ----
        {
            int tn = t + GRID;
            if (tn < NTILES) {
                const char* src = (const char*)(a + (size_t)tn * BM * FAN);
                uint32_t dst = sbase + OFF_STAGE;
#pragma unroll
                for (int it = 0; it < 16; ++it) {
                    uint32_t off = (uint32_t)tid * 16u + (uint32_t)it * 4096u;
                    CP_ASYNC16(dst + off, src + off);
                }
                CP_COMMIT();
            }
        }

        // ---- compute: 8 k-steps, 48 mma each ----
        float acc[2][8][4];
#pragma unroll
        for (int s = 0; s < 2; ++s)
#pragma unroll
            for (int nf = 0; nf < 8; ++nf)
#pragma unroll
                for (int e = 0; e < 4; ++e) acc[s][nf][e] = 0.0f;

#pragma unroll
        for (int ks = 0; ks < 8; ++ks) {
            const uint32_t blk = ((uint32_t)ks >> 2) << 14;
            const uint32_t kb = ((uint32_t)ks & 3) << 5;
            uint32_t bf[4][4], afh[2][4], afl[2][4];
#pragma unroll
            for (int q = 0; q < 4; ++q)
                LDSM4(bf[q], sWH + blk + rpB[q] + ((kb | kaddB) ^ axB[q]));
#pragma unroll
            for (int s = 0; s < 2; ++s) {
                LDSM4(afh[s], sAH + blk + rpA[s] + ((kb | kaddA) ^ axA[s]));
                LDSM4(afl[s], sAL + blk + rpA[s] + ((kb | kaddA) ^ axA[s]));
            }
            // AH*WH + AL*WH
#pragma unroll
            for (int s = 0; s < 2; ++s)
#pragma unroll
                for (int nf = 0; nf < 8; ++nf) {
                    const int q = nf >> 1, o = (nf & 1) << 1;
                    MMA16816(acc[s][nf], afh[s], bf[q][o], bf[q][o + 1]);
                    MMA16816(acc[s][nf], afl[s], bf[q][o], bf[q][o + 1]);
                }
            // AH*WL
#pragma unroll
            for (int q = 0; q < 4; ++q)
                LDSM4(bf[q], sWL + blk + rpB[q] + ((kb | kaddB) ^ axB[q]));
#pragma unroll
            for (int s = 0; s < 2; ++s)
#pragma unroll
                for (int nf = 0; nf < 8; ++nf) {
                    const int q = nf >> 1, o = (nf & 1) << 1;
                    MMA16816(acc[s][nf], afh[s], bf[q][o], bf[q][o + 1]);
                }
        }

        // ---- epilogue: bias (registers) + coalesced v2 stores ----
        {
            const int tq = lane >> 2;
            const int n_base = wn * 64 + (lane & 3) * 2;
            const size_t rowBase = (size_t)t * BM;
#pragma unroll
            for (int s = 0; s < 2; ++s) {
                size_t r0 = rowBase + (size_t)(wm * 32 + s * 16 + tq);
#pragma unroll
                for (int nf = 0; nf < 8; ++nf) {
                    int n0 = n_base + nf * 8;
                    float2 v0 = make_float2(acc[s][nf][0] + bx[nf], acc[s][nf][1] + by[nf]);
                    float2 v1 = make_float2(acc[s][nf][2] + bx[nf], acc[s][nf][3] + by[nf]);
                    *(float2*)(out + r0 * FAN + n0) = v0;
                    *(float2*)(out + (r0 + 8) * FAN + n0) = v1;
                }
            }
        }
    }
}

// ---------------------------------------------------------------------------
extern "C" void kernel_launch(void* const* d_in, const int* in_sizes, int n_in,
                              void* d_out, int out_size)
{
    const float* a = (const float*)d_in[0];
    const float* W = (const float*)d_in[1];
    const void* hidx = d_in[2];
    float* out = (float*)d_out;

    prep_kernel<<<64, 256>>>(W, hidx);

    cudaFuncSetAttribute(hashed_gemm_kernel,
                         cudaFuncAttributeMaxDynamicSharedMemorySize, SMEM_BYTES);
    hashed_gemm_kernel<<<GRID, 256, SMEM_BYTES>>>(a, out);
}

// round 9
// speedup vs baseline: 1.5718x; 1.5718x over previous
#include <cuda_runtime.h>
#include <cuda_fp16.h>
#include <cstdint>

// ============================================================================
// hashedLayer on GB300 (sm_103a SASS, PTX target compute_103 => NO tcgen05).
// out[b,i] = sum_j a_ext[b,j] * W[hash_idx[i,j]]
//          = a[B,128] @ Wmat[128,128]^T + bias[i],  bias[i]=W[hash_idx[i,128]]
// SINGLE-product fp16 mma.sync.m16n8k16 (fp32 accum). Global rel err ~4e-4
// (threshold 1e-3; R7 measured 4.4e-6 for the bf16-split variant, validating
// the error model). Persistent CTAs, 2-deep cp.async staging.
// ============================================================================

#define FAN 128
#define BM 128
#define NTILES 2048          // 262144 / 128
#define GRID 152
#define SW128(o) ((o) ^ (((o) >> 3) & 0x70))

// SMEM layout
#define OFF_BIAS  0                        // 512 B
#define OFF_WH    1024                     // 32 KB fp16 [128n x 128k] swizzled
#define OFF_A     (OFF_WH + 32768)         // 32 KB fp16 A tile
#define OFF_STAGE (OFF_A + 32768)          // 2 x 64 KB fp32 staging
#define SMEM_BYTES (OFF_STAGE + 2 * 65536) // 197632 < 227KB

// Tile byte offset: two 16KB blocks (k<64 / k>=64); within block
// off = row*128 + (k%64)*2, xor-swizzled for conflict-free ldmatrix.
static __device__ __host__ __forceinline__ uint32_t toff(int row, int k) {
    uint32_t off = (uint32_t)row * 128u + ((uint32_t)(k & 63) << 1);
    return (((uint32_t)k >> 6) << 14) + (uint32_t)SW128(off);
}

// W scratch (pre-swizzled fp16) + bias
__device__ __align__(16) __half g_wh[FAN * FAN];
__device__ float g_bias[FAN];

static __device__ __forceinline__ uint32_t smem_u32(const void* p) {
    uint32_t a;
    asm("{ .reg .u64 t; cvta.to.shared.u64 t, %1; cvt.u32.u64 %0, t; }"
        : "=r"(a) : "l"(p));
    return a;
}

#define LDSM4(r, addr) \
    asm volatile("ldmatrix.sync.aligned.m8n8.x4.shared.b16 {%0,%1,%2,%3}, [%4];" \
        : "=r"((r)[0]), "=r"((r)[1]), "=r"((r)[2]), "=r"((r)[3]) : "r"(addr))

#define MMA16816(d, a, b0, b1) \
    asm volatile("mma.sync.aligned.m16n8k16.row.col.f32.f16.f16.f32 " \
        "{%0,%1,%2,%3}, {%4,%5,%6,%7}, {%8,%9}, {%0,%1,%2,%3};" \
        : "+f"((d)[0]), "+f"((d)[1]), "+f"((d)[2]), "+f"((d)[3]) \
        : "r"((a)[0]), "r"((a)[1]), "r"((a)[2]), "r"((a)[3]), "r"(b0), "r"(b1))

#define CP_ASYNC16(dst, src) \
    asm volatile("cp.async.cg.shared.global [%0], [%1], 16;" \
        :: "r"(dst), "l"(src))
#define CP_COMMIT() asm volatile("cp.async.commit_group;" ::: "memory")
#define CP_WAIT1()  asm volatile("cp.async.wait_group 1;" ::: "memory")

// ---------------------------------------------------------------------------
// Kernel 1: gather Wmat = W[hash_idx] -> fp16 pre-swizzled; bias (fp32 exact).
// hash_idx may be int32 or int64 (JAX x64 ambiguity) — detect at runtime.
// ---------------------------------------------------------------------------
__global__ void __launch_bounds__(256) prep_kernel(
    const float* __restrict__ W, const void* __restrict__ hidx_raw)
{
    __shared__ int s_is64;
    if (threadIdx.x == 0) {
        // int64 values < 4096 -> odd int32 words all zero. P(false-pos) ~ 4096^-16
        const int* p32 = (const int*)hidx_raw;
        int any = 0;
#pragma unroll
        for (int k = 0; k < 16; ++k) any |= p32[2 * k + 1];
        s_is64 = (any == 0) ? 1 : 0;
    }
    __syncthreads();
    const int is64 = s_is64;
    const int* h32 = (const int*)hidx_raw;
    const long long* h64 = (const long long*)hidx_raw;

    int t = blockIdx.x * blockDim.x + threadIdx.x;
    if (t < FAN * FAN) {
        int i = t >> 7;              // output feature n
        int j = t & 127;             // reduction k
        size_t pos = (size_t)i * 129 + j;
        long long idx = is64 ? h64[pos] : (long long)h32[pos];
        float w = W[idx];
        uint32_t o = toff(i, j);
        g_wh[o >> 1] = __float2half_rn(w);
    }
    if (t < FAN) {
        size_t pos = (size_t)t * 129 + 128;
        long long idx = is64 ? h64[pos] : (long long)h32[pos];
        g_bias[t] = W[idx];
    }
}

// ---------------------------------------------------------------------------
// Kernel 2: persistent GEMM. 8 warps = 4(m) x 2(n), warp tile 32m x 64n.
// Per k-step: ldmatrix W(4x4) + A(2x4) -> 16 mma. 2-deep cp.async staging.
// ---------------------------------------------------------------------------
__global__ void __launch_bounds__(256, 1)
hashed_gemm_kernel(const float* __restrict__ a, float* __restrict__ out)
{
    extern __shared__ char smem[];
    const uint32_t sbase = smem_u32(smem);
    const int tid = threadIdx.x;
    const int wid = tid >> 5;
    const int lane = tid & 31;

    // ---- load W tile (already swizzled) + bias into SMEM ----
    {
        const uint4* sh = (const uint4*)g_wh;
        uint4* dh = (uint4*)(smem + OFF_WH);
#pragma unroll
        for (int it = 0; it < 8; ++it)
            dh[tid + it * 256] = sh[tid + it * 256];
        if (tid < FAN) ((float*)(smem + OFF_BIAS))[tid] = g_bias[tid];
    }

    // ---- per-lane ldmatrix address components ----
    const int g = lane >> 3, lr = lane & 7;
    const int wm = wid & 3;          // m block: rows wm*32
    const int wn = wid >> 2;         // n block: cols wn*64
    uint32_t rpA[2], axA[2], rpB[4], axB[4];
    const uint32_t kaddA = (uint32_t)((g >> 1) & 1) << 4;   // A: k+8 half
    const uint32_t kaddB = (uint32_t)(g & 1) << 4;          // B: k+8 half
#pragma unroll
    for (int s = 0; s < 2; ++s) {
        int row = wm * 32 + s * 16 + ((g & 1) << 3) + lr;   // A rows
        rpA[s] = (uint32_t)row << 7;
        axA[s] = (uint32_t)(row & 7) << 4;
    }
#pragma unroll
    for (int q = 0; q < 4; ++q) {
        int row = wn * 64 + q * 16 + (((g >> 1) & 1) << 3) + lr;  // B: n rows
        rpB[q] = (uint32_t)row << 7;
        axB[q] = (uint32_t)(row & 7) << 4;
    }
    const uint32_t sWH = sbase + OFF_WH;
    const uint32_t sA = sbase + OFF_A;

    // ---- preload per-thread bias pairs into registers (tile-invariant) ----
    __syncthreads();   // bias + W SMEM visible
    float bx[8], by[8];
    {
        const int tr = lane & 3;
        const float* bias_s = (const float*)(smem + OFF_BIAS);
#pragma unroll
        for (int nf = 0; nf < 8; ++nf) {
            int n0 = wn * 64 + nf * 8 + tr * 2;
            bx[nf] = bias_s[n0];
            by[nf] = bias_s[n0 + 1];
        }
    }

    // ---- prologue: stage tiles t0 and t0+GRID ----
    {
        const char* src0 = (const char*)(a + (size_t)blockIdx.x * BM * FAN);
        uint32_t dst0 = sbase + OFF_STAGE;
#pragma unroll
        for (int it = 0; it < 16; ++it) {
            uint32_t off = (uint32_t)tid * 16u + (uint32_t)it * 4096u;
            CP_ASYNC16(dst0 + off, src0 + off);
        }
        CP_COMMIT();
        int t1 = blockIdx.x + GRID;
        if (t1 < NTILES) {
            const char* src1 = (const char*)(a + (size_t)t1 * BM * FAN);
            uint32_t dst1 = sbase + OFF_STAGE + 65536u;
#pragma unroll
            for (int it = 0; it < 16; ++it) {
                uint32_t off = (uint32_t)tid * 16u + (uint32_t)it * 4096u;
                CP_ASYNC16(dst1 + off, src1 + off);
            }
        }
        CP_COMMIT();
    }

    int k = 0;
    for (int t = blockIdx.x; t < NTILES; t += GRID, ++k) {
        const int sb = k & 1;
        CP_WAIT1();         // group k (stage[sb]) complete; group k+1 may be in flight
        __syncthreads();

        // ---- convert stage[sb] (fp32) -> A (fp16, swizzled) ----
        {
            const float4* st4 = (const float4*)(smem + OFF_STAGE + (uint32_t)sb * 65536u);
#pragma unroll
            for (int it = 0; it < 16; ++it) {
                int idx = tid + it * 256;        // float4 index 0..4095
                float4 v = st4[idx];
                int row = idx >> 5;
                int kk = (idx & 31) << 2;
                __half2 h01 = __floats2half2_rn(v.x, v.y);
                __half2 h23 = __floats2half2_rn(v.z, v.w);
                uint2 hp;
                hp.x = *(uint32_t*)&h01; hp.y = *(uint32_t*)&h23;
                *(uint2*)(smem + OFF_A + toff(row, kk)) = hp;
            }
        }
        __syncthreads();    // STS visible before ldmatrix; stage[sb] fully consumed

        // ---- refill stage[sb] with tile t+2*GRID (overlaps compute) ----
        {
            int tn = t + 2 * GRID;
            if (tn < NTILES) {
                const char* src = (const char*)(a + (size_t)tn * BM * FAN);
                uint32_t dst = sbase + OFF_STAGE + (uint32_t)sb * 65536u;
#pragma unroll
                for (int it = 0; it < 16; ++it) {
                    uint32_t off = (uint32_t)tid * 16u + (uint32_t)it * 4096u;
                    CP_ASYNC16(dst + off, src + off);
                }
            }
            CP_COMMIT();    // commit unconditionally: group numbering stays aligned
        }

        // ---- compute: 8 k-steps, 16 mma each ----
        float acc[2][8][4];
#pragma unroll
        for (int s = 0; s < 2; ++s)
#pragma unroll
            for (int nf = 0; nf < 8; ++nf)
#pragma unroll
                for (int e = 0; e < 4; ++e) acc[s][nf][e] = 0.0f;

#pragma unroll
        for (int ks = 0; ks < 8; ++ks) {
            const uint32_t blk = ((uint32_t)ks >> 2) << 14;
            const uint32_t kb = ((uint32_t)ks & 3) << 5;
            uint32_t bf[4][4], af[2][4];
#pragma unroll
            for (int q = 0; q < 4; ++q)
                LDSM4(bf[q], sWH + blk + rpB[q] + ((kb | kaddB) ^ axB[q]));
#pragma unroll
            for (int s = 0; s < 2; ++s)
                LDSM4(af[s], sA + blk + rpA[s] + ((kb | kaddA) ^ axA[s]));
#pragma unroll
            for (int s = 0; s < 2; ++s)
#pragma unroll
                for (int nf = 0; nf < 8; ++nf) {
                    const int q = nf >> 1, o = (nf & 1) << 1;
                    MMA16816(acc[s][nf], af[s], bf[q][o], bf[q][o + 1]);
                }
        }

        // ---- epilogue: bias (registers) + coalesced v2 stores ----
        {
            const int tq = lane >> 2;
            const int n_base = wn * 64 + (lane & 3) * 2;
            const size_t rowBase = (size_t)t * BM;
#pragma unroll
            for (int s = 0; s < 2; ++s) {
                size_t r0 = rowBase + (size_t)(wm * 32 + s * 16 + tq);
#pragma unroll
                for (int nf = 0; nf < 8; ++nf) {
                    int n0 = n_base + nf * 8;
                    float2 v0 = make_float2(acc[s][nf][0] + bx[nf], acc[s][nf][1] + by[nf]);
                    float2 v1 = make_float2(acc[s][nf][2] + bx[nf], acc[s][nf][3] + by[nf]);
                    *(float2*)(out + r0 * FAN + n0) = v0;
                    *(float2*)(out + (r0 + 8) * FAN + n0) = v1;
                }
            }
        }
    }
}

// ---------------------------------------------------------------------------
extern "C" void kernel_launch(void* const* d_in, const int* in_sizes, int n_in,
                              void* d_out, int out_size)
{
    const float* a = (const float*)d_in[0];
    const float* W = (const float*)d_in[1];
    const void* hidx = d_in[2];
    float* out = (float*)d_out;

    prep_kernel<<<64, 256>>>(W, hidx);

    cudaFuncSetAttribute(hashed_gemm_kernel,
                         cudaFuncAttributeMaxDynamicSharedMemorySize, SMEM_BYTES);
    hashed_gemm_kernel<<<GRID, 256, SMEM_BYTES>>>(a, out);
}